// round 1
// baseline (speedup 1.0000x reference)
#include <cuda_runtime.h>
#include <math.h>

#define HH 320
#define WW 320
#define HWSZ (320*320)

// ---------------- scratch (static device globals; no allocation) -------------
__device__ float g_up[3*HWSZ];     // bicubic-upsampled query
__device__ float g_feat[64*HWSZ];  // [rf(0..31) | qf(32..63)]
__device__ float g_buf1[32*HWSZ];
__device__ float g_buf2[32*HWSZ];
__device__ float g_hid[32*HWSZ];

// ---------------- bicubic x2 (A = -0.75) -------------------------------------
__device__ __forceinline__ float cubicw(float t) {
    t = fabsf(t);
    if (t <= 1.0f) return ((1.25f*t - 2.25f)*t)*t + 1.0f;
    if (t <  2.0f) return -0.75f*((((t - 5.0f)*t + 8.0f)*t) - 4.0f);
    return 0.0f;
}

__global__ void bicubic_k(const float* __restrict__ q, float* __restrict__ o) {
    int idx = blockIdx.x*256 + threadIdx.x;            // 3*320*320 exact
    int ox = idx % 320;
    int t  = idx / 320;
    int oy = t % 320;
    int c  = t / 320;
    float sy = (oy + 0.5f)*0.5f - 0.5f;
    float sx = (ox + 0.5f)*0.5f - 0.5f;
    int iy0 = (int)floorf(sy), ix0 = (int)floorf(sx);
    float wy[4], wx[4]; int jy[4], jx[4];
    #pragma unroll
    for (int k = 0; k < 4; k++) {
        int ty = iy0 - 1 + k;
        wy[k] = cubicw(sy - (float)ty);
        jy[k] = min(max(ty, 0), 159);
        int tx = ix0 - 1 + k;
        wx[k] = cubicw(sx - (float)tx);
        jx[k] = min(max(tx, 0), 159);
    }
    const float* qc = q + c*160*160;
    float s = 0.0f;
    #pragma unroll
    for (int yy = 0; yy < 4; yy++) {
        float acc = 0.0f;
        #pragma unroll
        for (int xx = 0; xx < 4; xx++)
            acc += wx[xx]*__ldg(qc + jy[yy]*160 + jx[xx]);
        s += wy[yy]*acc;
    }
    o[idx] = s;
}

// ---------------- 5x5 conv, CIN -> 32, pad 2, lrelu(0.2) ---------------------
// block (16,8); tile 32w x 8h; 2 pixels / thread; 32 out channels in regs.
template<int CIN>
__global__ void conv5_lrelu(const float* __restrict__ in, const float* __restrict__ wt,
                            const float* __restrict__ bs, float* __restrict__ out) {
    __shared__ float s_in[12*36];
    __shared__ float s_w[32*25];
    const int tx = threadIdx.x, ty = threadIdx.y;
    const int tid = ty*16 + tx;
    const int ox0 = blockIdx.x*32, oy0 = blockIdx.y*8;
    float acc0[32], acc1[32];
    #pragma unroll
    for (int co = 0; co < 32; co++) { float b = __ldg(bs + co); acc0[co] = b; acc1[co] = b; }
    for (int ci = 0; ci < CIN; ci++) {
        __syncthreads();
        for (int i = tid; i < 12*36; i += 128) {
            int r = i/36, cc = i%36;
            int y = oy0 - 2 + r, x = ox0 - 2 + cc;
            s_in[i] = (y >= 0 && y < HH && x >= 0 && x < WW) ? in[ci*HWSZ + y*WW + x] : 0.0f;
        }
        for (int i = tid; i < 800; i += 128) {
            int co = i/25, k = i%25;
            s_w[i] = wt[(co*CIN + ci)*25 + k];
        }
        __syncthreads();
        #pragma unroll
        for (int ky = 0; ky < 5; ky++)
        #pragma unroll
        for (int kx = 0; kx < 5; kx++) {
            float v0 = s_in[(ty+ky)*36 + tx + kx];
            float v1 = s_in[(ty+ky)*36 + tx + 16 + kx];
            #pragma unroll
            for (int co = 0; co < 32; co++) {
                float wv = s_w[co*25 + ky*5 + kx];
                acc0[co] += v0*wv;
                acc1[co] += v1*wv;
            }
        }
    }
    int o = (oy0 + ty)*WW + ox0 + tx;
    #pragma unroll
    for (int co = 0; co < 32; co++) {
        float a0 = acc0[co]; a0 = (a0 >= 0.0f) ? a0 : 0.2f*a0;
        float a1 = acc1[co]; a1 = (a1 >= 0.0f) ? a1 : 0.2f*a1;
        out[co*HWSZ + o]      = a0;
        out[co*HWSZ + o + 16] = a1;
    }
}

// ---------------- 3x3 conv, 32 -> 32, pad 1 ----------------------------------
// MODE 0: out = relu(conv)    MODE 1: out = lrelu(conv + skip)
template<int MODE>
__global__ void conv3_k(const float* __restrict__ in, const float* __restrict__ wt,
                        const float* __restrict__ bs, const float* __restrict__ skip,
                        float* __restrict__ out) {
    __shared__ float s_in[10*34];
    __shared__ float s_w[32*9];
    const int tx = threadIdx.x, ty = threadIdx.y;
    const int tid = ty*16 + tx;
    const int ox0 = blockIdx.x*32, oy0 = blockIdx.y*8;
    float acc0[32], acc1[32];
    #pragma unroll
    for (int co = 0; co < 32; co++) { float b = __ldg(bs + co); acc0[co] = b; acc1[co] = b; }
    for (int ci = 0; ci < 32; ci++) {
        __syncthreads();
        for (int i = tid; i < 10*34; i += 128) {
            int r = i/34, cc = i%34;
            int y = oy0 - 1 + r, x = ox0 - 1 + cc;
            s_in[i] = (y >= 0 && y < HH && x >= 0 && x < WW) ? in[ci*HWSZ + y*WW + x] : 0.0f;
        }
        for (int i = tid; i < 288; i += 128) {
            int co = i/9, k = i%9;
            s_w[i] = wt[(co*32 + ci)*9 + k];
        }
        __syncthreads();
        #pragma unroll
        for (int ky = 0; ky < 3; ky++)
        #pragma unroll
        for (int kx = 0; kx < 3; kx++) {
            float v0 = s_in[(ty+ky)*34 + tx + kx];
            float v1 = s_in[(ty+ky)*34 + tx + 16 + kx];
            #pragma unroll
            for (int co = 0; co < 32; co++) {
                float wv = s_w[co*9 + ky*3 + kx];
                acc0[co] += v0*wv;
                acc1[co] += v1*wv;
            }
        }
    }
    int o = (oy0 + ty)*WW + ox0 + tx;
    #pragma unroll
    for (int co = 0; co < 32; co++) {
        float a0 = acc0[co], a1 = acc1[co];
        if (MODE == 0) {
            a0 = fmaxf(a0, 0.0f);
            a1 = fmaxf(a1, 0.0f);
        } else {
            a0 += skip[co*HWSZ + o];
            a1 += skip[co*HWSZ + o + 16];
            a0 = (a0 >= 0.0f) ? a0 : 0.2f*a0;
            a1 = (a1 >= 0.0f) ? a1 : 0.2f*a1;
        }
        out[co*HWSZ + o]      = a0;
        out[co*HWSZ + o + 16] = a1;
    }
}

// ---------------- fused 1x1 affine head + deformable 2x2 bilinear sampler ----
__device__ __forceinline__ int reflect_idx(int i) {  // xp coord -> x coord
    int r = i - 1;
    r = (r < 0) ? -r : r;
    r = (r > 319) ? (638 - r) : r;
    return r;
}

__global__ void sampler_k(const float* __restrict__ hid, const float* __restrict__ w2,
                          const float* __restrict__ b2, const float* __restrict__ x,
                          float* __restrict__ out) {
    __shared__ float s_w2[96];
    int tid = threadIdx.x;
    if (tid < 96) s_w2[tid] = w2[tid];
    __syncthreads();
    int p = blockIdx.x*256 + tid;                    // 102400 exact
    int h = p / WW, w = p % WW;

    float a0 = __ldg(b2 + 0), a1 = __ldg(b2 + 1), a2 = __ldg(b2 + 2);
    #pragma unroll 4
    for (int c = 0; c < 32; c++) {
        float hv = hid[c*HWSZ + p];
        a0 += hv*s_w2[c];
        a1 += hv*s_w2[32 + c];
        a2 += hv*s_w2[64 + c];
    }
    a0 = fminf(fmaxf(a0 + 1.0f, -3.0f), 3.0f);       // s_x
    a1 = fminf(fmaxf(a1 + 1.0f, -3.0f), 3.0f);       // s_y
    a2 = fminf(fmaxf(a2 + 1.0f, -3.0f), 3.0f);
    float th = (a2 - 1.0f)*1.0472f;
    float ct = cosf(th), st = sinf(th);

    int   idx[16];
    float wg[16];
    #pragma unroll
    for (int k = 0; k < 4; k++) {
        float pnx = (k & 2) ? 0.5f : -0.5f;
        float pny = (k & 1) ? 0.5f : -0.5f;
        float px = pnx*a0, py = pny*a1;
        float rx = px*ct - py*st;
        float ry = px*st + py*ct;
        float p_x = rx + 0.5f + (float)(h + 1);
        float p_y = ry + 0.5f + (float)(w + 1);
        float ltx = floorf(p_x), lty = floorf(p_y);
        float ltxc = fminf(fmaxf(ltx,        0.0f), 321.0f);
        float ltyc = fminf(fmaxf(lty,        0.0f), 321.0f);
        float rbxc = fminf(fmaxf(ltx + 1.0f, 0.0f), 321.0f);
        float rbyc = fminf(fmaxf(lty + 1.0f, 0.0f), 321.0f);
        float pxc  = fminf(fmaxf(p_x,        0.0f), 321.0f);
        float pyc  = fminf(fmaxf(p_y,        0.0f), 321.0f);
        float wlx = 1.0f + ltxc - pxc;
        float wrx = 1.0f - (rbxc - pxc);
        float wly = 1.0f + ltyc - pyc;
        float wry = 1.0f - (rbyc - pyc);
        int rl = reflect_idx((int)ltxc);
        int rr = reflect_idx((int)rbxc);
        int cl = reflect_idx((int)ltyc);
        int cr = reflect_idx((int)rbyc);
        idx[k*4+0] = rl*WW + cl;  wg[k*4+0] = wlx*wly;   // lt
        idx[k*4+1] = rr*WW + cr;  wg[k*4+1] = wrx*wry;   // rb
        idx[k*4+2] = rl*WW + cr;  wg[k*4+2] = wlx*wry;   // lb
        idx[k*4+3] = rr*WW + cl;  wg[k*4+3] = wrx*wly;   // rt
    }

    int ob = (2*h)*640 + 2*w;
    for (int c = 0; c < 64; c++) {
        const float* xc = x + c*HWSZ;
        float* oc = out + c*640*640;
        #pragma unroll
        for (int k = 0; k < 4; k++) {
            float v = wg[k*4+0]*__ldg(xc + idx[k*4+0])
                    + wg[k*4+1]*__ldg(xc + idx[k*4+1])
                    + wg[k*4+2]*__ldg(xc + idx[k*4+2])
                    + wg[k*4+3]*__ldg(xc + idx[k*4+3]);
            oc[ob + (k >> 1)*640 + (k & 1)] = v;
        }
    }
}

// ---------------- launch ------------------------------------------------------
extern "C" void kernel_launch(void* const* d_in, const int* in_sizes, int n_in,
                              void* d_out, int out_size) {
    const float* x    = (const float*)d_in[0];
    const float* qry  = (const float*)d_in[1];
    const float* ref  = (const float*)d_in[2];
    const float* c1w  = (const float*)d_in[3];
    const float* c1b  = (const float*)d_in[4];
    const float* r1w1 = (const float*)d_in[5];
    const float* r1b1 = (const float*)d_in[6];
    const float* r1w2 = (const float*)d_in[7];
    const float* r1b2 = (const float*)d_in[8];
    const float* p1w  = (const float*)d_in[9];
    const float* p1b  = (const float*)d_in[10];
    const float* prw1 = (const float*)d_in[11];
    const float* prb1 = (const float*)d_in[12];
    const float* prw2 = (const float*)d_in[13];
    const float* prb2 = (const float*)d_in[14];
    const float* p2w  = (const float*)d_in[15];
    const float* p2b  = (const float*)d_in[16];
    float* out = (float*)d_out;

    float *up, *feat, *buf1, *buf2, *hid;
    cudaGetSymbolAddress((void**)&up,   g_up);
    cudaGetSymbolAddress((void**)&feat, g_feat);
    cudaGetSymbolAddress((void**)&buf1, g_buf1);
    cudaGetSymbolAddress((void**)&buf2, g_buf2);
    cudaGetSymbolAddress((void**)&hid,  g_hid);

    dim3 cb(16, 8);
    dim3 cg(10, 40);   // 320/32 x 320/8 = 400 blocks

    // 1. bicubic upsample query 160->320
    bicubic_k<<<(3*HWSZ)/256, 256>>>(qry, up);

    // 2. feat_head(ref) -> feat[0..31]
    conv5_lrelu<3><<<cg, cb>>>(ref, c1w, c1b, buf1);
    conv3_k<0><<<cg, cb>>>(buf1, r1w1, r1b1, nullptr, buf2);
    conv3_k<1><<<cg, cb>>>(buf2, r1w2, r1b2, buf1, feat);

    // 3. feat_head(up(query)) -> feat[32..63]
    conv5_lrelu<3><<<cg, cb>>>(up, c1w, c1b, buf1);
    conv3_k<0><<<cg, cb>>>(buf1, r1w1, r1b1, nullptr, buf2);
    conv3_k<1><<<cg, cb>>>(buf2, r1w2, r1b2, buf1, feat + 32*HWSZ);

    // 4. fusion head: p1 5x5 64->32 + lrelu, then resblock + lrelu
    conv5_lrelu<64><<<cg, cb>>>(feat, p1w, p1b, buf1);
    conv3_k<0><<<cg, cb>>>(buf1, prw1, prb1, nullptr, buf2);
    conv3_k<1><<<cg, cb>>>(buf2, prw2, prb2, buf1, hid);

    // 5. fused 1x1 affine head + deformable sampler -> out (64,640,640)
    sampler_k<<<HWSZ/256, 256>>>(hid, p2w, p2b, x, out);
}

// round 2
// speedup vs baseline: 1.6095x; 1.6095x over previous
#include <cuda_runtime.h>
#include <math.h>

#define HH 320
#define WW 320
#define HWSZ (320*320)

// ---------------- scratch (static device globals; no allocation) -------------
__device__ float g_up[3*HWSZ];      // bicubic-upsampled query
__device__ float g_feat[64*HWSZ];   // [rf(0..31) | qf(32..63)]
__device__ float g_buf1[64*HWSZ];   // 2 images x 32 ch
__device__ float g_buf2[64*HWSZ];
__device__ float g_hid[32*HWSZ];

typedef unsigned long long u64;

// ---------------- packed f32x2 helpers (sm_103a FFMA2) -----------------------
__device__ __forceinline__ u64 pack2(float a, float b) {
    u64 r; asm("mov.b64 %0,{%1,%2};" : "=l"(r) : "f"(a), "f"(b)); return r;
}
__device__ __forceinline__ void unpack2(u64 v, float& a, float& b) {
    asm("mov.b64 {%0,%1},%2;" : "=f"(a), "=f"(b) : "l"(v));
}
__device__ __forceinline__ u64 fma2(u64 a, u64 b, u64 c) {
    u64 d; asm("fma.rn.f32x2 %0,%1,%2,%3;" : "=l"(d) : "l"(a), "l"(b), "l"(c)); return d;
}

// ---------------- bicubic x2 (A = -0.75) -------------------------------------
__device__ __forceinline__ float cubicw(float t) {
    t = fabsf(t);
    if (t <= 1.0f) return ((1.25f*t - 2.25f)*t)*t + 1.0f;
    if (t <  2.0f) return -0.75f*((((t - 5.0f)*t + 8.0f)*t) - 4.0f);
    return 0.0f;
}

__global__ void bicubic_k(const float* __restrict__ q, float* __restrict__ o) {
    int idx = blockIdx.x*256 + threadIdx.x;            // 3*320*320 exact
    int ox = idx % 320;
    int t  = idx / 320;
    int oy = t % 320;
    int c  = t / 320;
    float sy = (oy + 0.5f)*0.5f - 0.5f;
    float sx = (ox + 0.5f)*0.5f - 0.5f;
    int iy0 = (int)floorf(sy), ix0 = (int)floorf(sx);
    float wy[4], wx[4]; int jy[4], jx[4];
    #pragma unroll
    for (int k = 0; k < 4; k++) {
        int ty = iy0 - 1 + k;
        wy[k] = cubicw(sy - (float)ty);
        jy[k] = min(max(ty, 0), 159);
        int tx = ix0 - 1 + k;
        wx[k] = cubicw(sx - (float)tx);
        jx[k] = min(max(tx, 0), 159);
    }
    const float* qc = q + c*160*160;
    float s = 0.0f;
    #pragma unroll
    for (int yy = 0; yy < 4; yy++) {
        float acc = 0.0f;
        #pragma unroll
        for (int xx = 0; xx < 4; xx++)
            acc += wx[xx]*__ldg(qc + jy[yy]*160 + jx[xx]);
        s += wy[yy]*acc;
    }
    o[idx] = s;
}

// ---------------- 3x3 conv, 32->32, pad 1, dual image (gridDim.z) ------------
// tile 32x8, 256 threads, 1 px/thread, 32 out channels as 16 f32x2 pairs.
// MODE 0: relu(conv)   MODE 1: lrelu(conv + skip)
#define C3_SIN (32*340)
#define C3_SW  (32*288)
#define C3_SMEM ((C3_SIN + C3_SW)*4)

template<int MODE>
__global__ void __launch_bounds__(256, 2) conv3_k(
    const float* __restrict__ in0, const float* __restrict__ in1,
    const float* __restrict__ wt,  const float* __restrict__ bs,
    const float* __restrict__ sk0, const float* __restrict__ sk1,
    float* __restrict__ out0, float* __restrict__ out1)
{
    extern __shared__ float sm[];
    float* s_in = sm;             // [ci][10][34]
    float* s_w  = sm + C3_SIN;    // [ci][9][co=32]
    const float* in = blockIdx.z ? in1 : in0;
    const float* sk = blockIdx.z ? sk1 : sk0;
    float* out      = blockIdx.z ? out1 : out0;
    const int tx = threadIdx.x, ty = threadIdx.y;
    const int tid = ty*32 + tx;
    const int ox0 = blockIdx.x*32, oy0 = blockIdx.y*8;

    for (int i = tid; i < C3_SIN; i += 256) {
        int ci = i / 340, rem = i % 340;
        int r = rem / 34, cc = rem % 34;
        int y = oy0 - 1 + r, x = ox0 - 1 + cc;
        s_in[i] = (y >= 0 && y < HH && x >= 0 && x < WW) ? in[ci*HWSZ + y*WW + x] : 0.0f;
    }
    for (int i = tid; i < C3_SW; i += 256) {
        int ci = i / 288, rem = i % 288;
        int k = rem >> 5, co = rem & 31;
        s_w[i] = wt[(co*32 + ci)*9 + k];
    }
    __syncthreads();

    u64 acc[16];
    #pragma unroll
    for (int cp = 0; cp < 16; cp++) acc[cp] = pack2(__ldg(bs + 2*cp), __ldg(bs + 2*cp + 1));

    for (int ci = 0; ci < 32; ci++) {
        const float* si = s_in + ci*340 + ty*34 + tx;
        const float* sw = s_w + ci*288;
        #pragma unroll
        for (int ky = 0; ky < 3; ky++)
        #pragma unroll
        for (int kx = 0; kx < 3; kx++) {
            float v = si[ky*34 + kx];
            u64 vp = pack2(v, v);
            const float* wr = sw + (ky*3 + kx)*32;
            #pragma unroll
            for (int cp = 0; cp < 16; cp++) {
                u64 wp = *(const u64*)(wr + cp*2);
                acc[cp] = fma2(vp, wp, acc[cp]);
            }
        }
    }

    int o = (oy0 + ty)*WW + ox0 + tx;
    #pragma unroll
    for (int cp = 0; cp < 16; cp++) {
        float a0, a1; unpack2(acc[cp], a0, a1);
        if (MODE == 0) {
            a0 = fmaxf(a0, 0.0f); a1 = fmaxf(a1, 0.0f);
        } else {
            a0 += sk[(2*cp)*HWSZ + o];
            a1 += sk[(2*cp + 1)*HWSZ + o];
            a0 = (a0 >= 0.0f) ? a0 : 0.2f*a0;
            a1 = (a1 >= 0.0f) ? a1 : 0.2f*a1;
        }
        out[(2*cp)*HWSZ + o]     = a0;
        out[(2*cp + 1)*HWSZ + o] = a1;
    }
}

// ---------------- 5x5 conv, CIN->32, pad 2, lrelu, dual image ----------------
template<int CIN, int CHUNK>
__global__ void __launch_bounds__(256, 2) conv5_k(
    const float* __restrict__ in0, const float* __restrict__ in1,
    const float* __restrict__ wt,  const float* __restrict__ bs,
    float* __restrict__ out0, float* __restrict__ out1)
{
    extern __shared__ float sm[];
    float* s_in = sm;                 // [CHUNK][12][36]
    float* s_w  = sm + CHUNK*432;     // [CHUNK][25][32]
    const float* in = blockIdx.z ? in1 : in0;
    float* out      = blockIdx.z ? out1 : out0;
    const int tx = threadIdx.x, ty = threadIdx.y;
    const int tid = ty*32 + tx;
    const int ox0 = blockIdx.x*32, oy0 = blockIdx.y*8;

    u64 acc[16];
    #pragma unroll
    for (int cp = 0; cp < 16; cp++) acc[cp] = pack2(__ldg(bs + 2*cp), __ldg(bs + 2*cp + 1));

    for (int c0 = 0; c0 < CIN; c0 += CHUNK) {
        __syncthreads();
        for (int i = tid; i < CHUNK*432; i += 256) {
            int ci = i / 432, rem = i % 432;
            int r = rem / 36, cc = rem % 36;
            int y = oy0 - 2 + r, x = ox0 - 2 + cc;
            s_in[i] = (y >= 0 && y < HH && x >= 0 && x < WW) ? in[(c0 + ci)*HWSZ + y*WW + x] : 0.0f;
        }
        for (int i = tid; i < CHUNK*800; i += 256) {
            int ci = i / 800, rem = i % 800;
            int k = rem >> 5, co = rem & 31;
            s_w[i] = wt[(co*CIN + c0 + ci)*25 + k];
        }
        __syncthreads();

        for (int ci = 0; ci < CHUNK; ci++) {
            const float* si = s_in + ci*432 + ty*36 + tx;
            const float* sw = s_w + ci*800;
            #pragma unroll
            for (int ky = 0; ky < 5; ky++)
            #pragma unroll
            for (int kx = 0; kx < 5; kx++) {
                float v = si[ky*36 + kx];
                u64 vp = pack2(v, v);
                const float* wr = sw + (ky*5 + kx)*32;
                #pragma unroll
                for (int cp = 0; cp < 16; cp++) {
                    u64 wp = *(const u64*)(wr + cp*2);
                    acc[cp] = fma2(vp, wp, acc[cp]);
                }
            }
        }
    }

    int o = (oy0 + ty)*WW + ox0 + tx;
    #pragma unroll
    for (int cp = 0; cp < 16; cp++) {
        float a0, a1; unpack2(acc[cp], a0, a1);
        a0 = (a0 >= 0.0f) ? a0 : 0.2f*a0;
        a1 = (a1 >= 0.0f) ? a1 : 0.2f*a1;
        out[(2*cp)*HWSZ + o]     = a0;
        out[(2*cp + 1)*HWSZ + o] = a1;
    }
}

// ---------------- fused 1x1 affine head + deformable 2x2 bilinear sampler ----
__device__ __forceinline__ int reflect_idx(int i) {  // xp coord -> x coord
    int r = i - 1;
    r = (r < 0) ? -r : r;
    r = (r > 319) ? (638 - r) : r;
    return r;
}

__global__ void sampler_k(const float* __restrict__ hid, const float* __restrict__ w2,
                          const float* __restrict__ b2, const float* __restrict__ x,
                          float* __restrict__ out) {
    __shared__ float s_w2[96];
    int tid = threadIdx.x;
    if (tid < 96) s_w2[tid] = w2[tid];
    __syncthreads();
    int p = blockIdx.x*256 + tid;                    // 102400 exact
    int h = p / WW, w = p % WW;

    float a0 = __ldg(b2 + 0), a1 = __ldg(b2 + 1), a2 = __ldg(b2 + 2);
    #pragma unroll 4
    for (int c = 0; c < 32; c++) {
        float hv = hid[c*HWSZ + p];
        a0 += hv*s_w2[c];
        a1 += hv*s_w2[32 + c];
        a2 += hv*s_w2[64 + c];
    }
    a0 = fminf(fmaxf(a0 + 1.0f, -3.0f), 3.0f);       // s_x
    a1 = fminf(fmaxf(a1 + 1.0f, -3.0f), 3.0f);       // s_y
    a2 = fminf(fmaxf(a2 + 1.0f, -3.0f), 3.0f);
    float th = (a2 - 1.0f)*1.0472f;
    float ct = cosf(th), st = sinf(th);

    int   idx[16];
    float wg[16];
    #pragma unroll
    for (int k = 0; k < 4; k++) {
        float pnx = (k & 2) ? 0.5f : -0.5f;
        float pny = (k & 1) ? 0.5f : -0.5f;
        float px = pnx*a0, py = pny*a1;
        float rx = px*ct - py*st;
        float ry = px*st + py*ct;
        float p_x = rx + 0.5f + (float)(h + 1);
        float p_y = ry + 0.5f + (float)(w + 1);
        float ltx = floorf(p_x), lty = floorf(p_y);
        float ltxc = fminf(fmaxf(ltx,        0.0f), 321.0f);
        float ltyc = fminf(fmaxf(lty,        0.0f), 321.0f);
        float rbxc = fminf(fmaxf(ltx + 1.0f, 0.0f), 321.0f);
        float rbyc = fminf(fmaxf(lty + 1.0f, 0.0f), 321.0f);
        float pxc  = fminf(fmaxf(p_x,        0.0f), 321.0f);
        float pyc  = fminf(fmaxf(p_y,        0.0f), 321.0f);
        float wlx = 1.0f + ltxc - pxc;
        float wrx = 1.0f - (rbxc - pxc);
        float wly = 1.0f + ltyc - pyc;
        float wry = 1.0f - (rbyc - pyc);
        int rl = reflect_idx((int)ltxc);
        int rr = reflect_idx((int)rbxc);
        int cl = reflect_idx((int)ltyc);
        int cr = reflect_idx((int)rbyc);
        idx[k*4+0] = rl*WW + cl;  wg[k*4+0] = wlx*wly;   // lt
        idx[k*4+1] = rr*WW + cr;  wg[k*4+1] = wrx*wry;   // rb
        idx[k*4+2] = rl*WW + cr;  wg[k*4+2] = wlx*wry;   // lb
        idx[k*4+3] = rr*WW + cl;  wg[k*4+3] = wrx*wly;   // rt
    }

    int ob = (2*h)*640 + 2*w;
    for (int c = 0; c < 64; c++) {
        const float* xc = x + c*HWSZ;
        float* oc = out + c*640*640;
        float v[4];
        #pragma unroll
        for (int k = 0; k < 4; k++) {
            v[k] = wg[k*4+0]*__ldg(xc + idx[k*4+0])
                 + wg[k*4+1]*__ldg(xc + idx[k*4+1])
                 + wg[k*4+2]*__ldg(xc + idx[k*4+2])
                 + wg[k*4+3]*__ldg(xc + idx[k*4+3]);
        }
        *(float2*)(oc + ob)       = make_float2(v[0], v[1]);
        *(float2*)(oc + ob + 640) = make_float2(v[2], v[3]);
    }
}

// ---------------- launch ------------------------------------------------------
extern "C" void kernel_launch(void* const* d_in, const int* in_sizes, int n_in,
                              void* d_out, int out_size) {
    const float* x    = (const float*)d_in[0];
    const float* qry  = (const float*)d_in[1];
    const float* ref  = (const float*)d_in[2];
    const float* c1w  = (const float*)d_in[3];
    const float* c1b  = (const float*)d_in[4];
    const float* r1w1 = (const float*)d_in[5];
    const float* r1b1 = (const float*)d_in[6];
    const float* r1w2 = (const float*)d_in[7];
    const float* r1b2 = (const float*)d_in[8];
    const float* p1w  = (const float*)d_in[9];
    const float* p1b  = (const float*)d_in[10];
    const float* prw1 = (const float*)d_in[11];
    const float* prb1 = (const float*)d_in[12];
    const float* prw2 = (const float*)d_in[13];
    const float* prb2 = (const float*)d_in[14];
    const float* p2w  = (const float*)d_in[15];
    const float* p2b  = (const float*)d_in[16];
    float* out = (float*)d_out;

    float *up, *feat, *buf1, *buf2, *hid;
    cudaGetSymbolAddress((void**)&up,   g_up);
    cudaGetSymbolAddress((void**)&feat, g_feat);
    cudaGetSymbolAddress((void**)&buf1, g_buf1);
    cudaGetSymbolAddress((void**)&buf2, g_buf2);
    cudaGetSymbolAddress((void**)&hid,  g_hid);

    const int SM3   = C3_SMEM;                  // 80384 B
    const int SM5_3 = (3*432 + 3*800)*4;        // 14784 B
    const int SM5_64= (16*432 + 16*800)*4;      // 78848 B
    cudaFuncSetAttribute(conv3_k<0>, cudaFuncAttributeMaxDynamicSharedMemorySize, SM3);
    cudaFuncSetAttribute(conv3_k<1>, cudaFuncAttributeMaxDynamicSharedMemorySize, SM3);
    cudaFuncSetAttribute(conv5_k<3,3>,   cudaFuncAttributeMaxDynamicSharedMemorySize, SM5_3);
    cudaFuncSetAttribute(conv5_k<64,16>, cudaFuncAttributeMaxDynamicSharedMemorySize, SM5_64);

    dim3 cb(32, 8);
    dim3 cg2(10, 40, 2);
    dim3 cg1(10, 40, 1);

    // 1. bicubic upsample query 160->320
    bicubic_k<<<(3*HWSZ)/256, 256>>>(qry, up);

    // 2+3. both feature heads batched over gridDim.z
    conv5_k<3,3><<<cg2, cb, SM5_3>>>(ref, up, c1w, c1b, buf1, buf1 + 32*HWSZ);
    conv3_k<0><<<cg2, cb, SM3>>>(buf1, buf1 + 32*HWSZ, r1w1, r1b1,
                                 nullptr, nullptr, buf2, buf2 + 32*HWSZ);
    conv3_k<1><<<cg2, cb, SM3>>>(buf2, buf2 + 32*HWSZ, r1w2, r1b2,
                                 buf1, buf1 + 32*HWSZ, feat, feat + 32*HWSZ);

    // 4. fusion head
    conv5_k<64,16><<<cg1, cb, SM5_64>>>(feat, feat, p1w, p1b, buf1, buf1);
    conv3_k<0><<<cg1, cb, SM3>>>(buf1, buf1, prw1, prb1, nullptr, nullptr, buf2, buf2);
    conv3_k<1><<<cg1, cb, SM3>>>(buf2, buf2, prw2, prb2, buf1, buf1, hid, hid);

    // 5. fused 1x1 affine head + deformable sampler -> out (64,640,640)
    sampler_k<<<HWSZ/256, 256>>>(hid, p2w, p2b, x, out);
}

// round 4
// speedup vs baseline: 2.1875x; 1.3591x over previous
#include <cuda_runtime.h>
#include <math.h>

#define HH 320
#define WW 320
#define HWSZ (320*320)

// ---------------- scratch (static device globals; no allocation) -------------
__device__ float g_up[3*HWSZ];      // bicubic-upsampled query
__device__ float g_feat[64*HWSZ];   // [rf(0..31) | qf(32..63)]
__device__ float g_buf1[64*HWSZ];   // 2 images x 32 ch
__device__ float g_buf2[64*HWSZ];
__device__ float g_hid[32*HWSZ];

typedef unsigned long long u64;

// ---------------- packed f32x2 helpers (sm_103a FFMA2) -----------------------
__device__ __forceinline__ u64 pack2(float a, float b) {
    u64 r; asm("mov.b64 %0,{%1,%2};" : "=l"(r) : "f"(a), "f"(b)); return r;
}
__device__ __forceinline__ void unpack2(u64 v, float& a, float& b) {
    asm("mov.b64 {%0,%1},%2;" : "=f"(a), "=f"(b) : "l"(v));
}
__device__ __forceinline__ u64 fma2(u64 a, u64 b, u64 c) {
    u64 d; asm("fma.rn.f32x2 %0,%1,%2,%3;" : "=l"(d) : "l"(a), "l"(b), "l"(c)); return d;
}

// ---------------- bicubic x2 (A = -0.75) -------------------------------------
__device__ __forceinline__ float cubicw(float t) {
    t = fabsf(t);
    if (t <= 1.0f) return ((1.25f*t - 2.25f)*t)*t + 1.0f;
    if (t <  2.0f) return -0.75f*((((t - 5.0f)*t + 8.0f)*t) - 4.0f);
    return 0.0f;
}

__global__ void bicubic_k(const float* __restrict__ q, float* __restrict__ o) {
    int idx = blockIdx.x*256 + threadIdx.x;            // 3*320*320 exact
    int ox = idx % 320;
    int t  = idx / 320;
    int oy = t % 320;
    int c  = t / 320;
    float sy = (oy + 0.5f)*0.5f - 0.5f;
    float sx = (ox + 0.5f)*0.5f - 0.5f;
    int iy0 = (int)floorf(sy), ix0 = (int)floorf(sx);
    float wy[4], wx[4]; int jy[4], jx[4];
    #pragma unroll
    for (int k = 0; k < 4; k++) {
        int ty = iy0 - 1 + k;
        wy[k] = cubicw(sy - (float)ty);
        jy[k] = min(max(ty, 0), 159);
        int tx = ix0 - 1 + k;
        wx[k] = cubicw(sx - (float)tx);
        jx[k] = min(max(tx, 0), 159);
    }
    const float* qc = q + c*160*160;
    float s = 0.0f;
    #pragma unroll
    for (int yy = 0; yy < 4; yy++) {
        float acc = 0.0f;
        #pragma unroll
        for (int xx = 0; xx < 4; xx++)
            acc += wx[xx]*__ldg(qc + jy[yy]*160 + jx[xx]);
        s += wy[yy]*acc;
    }
    o[idx] = s;
}

// ---------------- 3x3 conv, 32->32, pad 1, dual image (gridDim.z) ------------
// tile 64x8; 256 threads; thread = 4 consecutive px x 16 channels (2 co-groups)
// smem input row stride padded to 68 floats for 16B-aligned float4 LDS.
// MODE 0: relu(conv)   MODE 1: lrelu(conv + skip)
#define C3_CHUNK 16
#define C3_RS   68                      // padded row stride (floats)
#define C3_CIS  (10*C3_RS)              // 680 floats per ci
#define C3_SIN  (C3_CHUNK*C3_CIS)       // 10880 floats
#define C3_SW   (C3_CHUNK*9*32)         // 4608 floats
#define C3_SMEM ((C3_SIN + C3_SW)*4)    // 61952 B

template<int MODE>
__global__ void __launch_bounds__(256, 2) conv3_k(
    const float* __restrict__ in0, const float* __restrict__ in1,
    const float* __restrict__ wt,  const float* __restrict__ bs,
    const float* __restrict__ sk0, const float* __restrict__ sk1,
    float* __restrict__ out0, float* __restrict__ out1)
{
    extern __shared__ float sm[];
    float* s_in = sm;             // [ci][10][68 (66 used)]
    float* s_w  = sm + C3_SIN;    // [ci][9][32co]
    const float* in = blockIdx.z ? in1 : in0;
    const float* sk = blockIdx.z ? sk1 : sk0;
    float* out      = blockIdx.z ? out1 : out0;
    const int tid = threadIdx.x;
    const int txg = tid & 15;          // 16 x-groups (4 px each)
    const int ty  = (tid >> 4) & 7;    // 8 rows
    const int cog = tid >> 7;          // 2 channel groups (16 co each)
    const int ox0 = blockIdx.x*64, oy0 = blockIdx.y*8;

    u64 acc[4][8];
    #pragma unroll
    for (int cp = 0; cp < 8; cp++) {
        u64 b = pack2(__ldg(bs + cog*16 + 2*cp), __ldg(bs + cog*16 + 2*cp + 1));
        #pragma unroll
        for (int p = 0; p < 4; p++) acc[p][cp] = b;
    }

    for (int c0 = 0; c0 < 32; c0 += C3_CHUNK) {
        if (c0) __syncthreads();
        // fill 66 used columns per row (stride 68; cols 66,67 unused)
        for (int i = tid; i < C3_CHUNK*10*66; i += 256) {
            int ci = i / 660, rem = i % 660;
            int r = rem / 66, cc = rem % 66;
            int y = oy0 - 1 + r, x = ox0 - 1 + cc;
            s_in[ci*C3_CIS + r*C3_RS + cc] =
                (y >= 0 && y < HH && x >= 0 && x < WW) ? in[(c0+ci)*HWSZ + y*WW + x] : 0.0f;
        }
        for (int i = tid; i < C3_SW; i += 256) {
            int ci = i / 288, rem = i % 288;
            int k = rem >> 5, co = rem & 31;
            s_w[i] = wt[(co*32 + c0 + ci)*9 + k];
        }
        __syncthreads();

        for (int ci = 0; ci < C3_CHUNK; ci++) {
            const float* base = s_in + ci*C3_CIS + ty*C3_RS + txg*4;
            const float* wci  = s_w + ci*288 + cog*16;
            #pragma unroll
            for (int ky = 0; ky < 3; ky++) {
                const float* rp = base + ky*C3_RS;
                float4 v4 = *(const float4*)rp;
                float2 v2 = *(const float2*)(rp + 4);
                u64 vp[6];
                vp[0]=pack2(v4.x,v4.x); vp[1]=pack2(v4.y,v4.y); vp[2]=pack2(v4.z,v4.z);
                vp[3]=pack2(v4.w,v4.w); vp[4]=pack2(v2.x,v2.x); vp[5]=pack2(v2.y,v2.y);
                #pragma unroll
                for (int kx = 0; kx < 3; kx++) {
                    const float* wr = wci + (ky*3 + kx)*32;
                    u64 w[8];
                    #pragma unroll
                    for (int cp = 0; cp < 8; cp++) w[cp] = *(const u64*)(wr + 2*cp);
                    #pragma unroll
                    for (int p = 0; p < 4; p++)
                        #pragma unroll
                        for (int cp = 0; cp < 8; cp++)
                            acc[p][cp] = fma2(vp[p+kx], w[cp], acc[p][cp]);
                }
            }
        }
    }

    int o = (oy0 + ty)*WW + ox0 + txg*4;
    #pragma unroll
    for (int cp = 0; cp < 8; cp++) {
        int coe = cog*16 + 2*cp;
        float4 ve, vo;
        unpack2(acc[0][cp], ve.x, vo.x);
        unpack2(acc[1][cp], ve.y, vo.y);
        unpack2(acc[2][cp], ve.z, vo.z);
        unpack2(acc[3][cp], ve.w, vo.w);
        if (MODE == 0) {
            ve.x=fmaxf(ve.x,0.f); ve.y=fmaxf(ve.y,0.f); ve.z=fmaxf(ve.z,0.f); ve.w=fmaxf(ve.w,0.f);
            vo.x=fmaxf(vo.x,0.f); vo.y=fmaxf(vo.y,0.f); vo.z=fmaxf(vo.z,0.f); vo.w=fmaxf(vo.w,0.f);
        } else {
            float4 se = *(const float4*)(sk + coe*HWSZ + o);
            float4 so = *(const float4*)(sk + (coe+1)*HWSZ + o);
            ve.x+=se.x; ve.y+=se.y; ve.z+=se.z; ve.w+=se.w;
            vo.x+=so.x; vo.y+=so.y; vo.z+=so.z; vo.w+=so.w;
            ve.x=(ve.x>=0.f)?ve.x:0.2f*ve.x; ve.y=(ve.y>=0.f)?ve.y:0.2f*ve.y;
            ve.z=(ve.z>=0.f)?ve.z:0.2f*ve.z; ve.w=(ve.w>=0.f)?ve.w:0.2f*ve.w;
            vo.x=(vo.x>=0.f)?vo.x:0.2f*vo.x; vo.y=(vo.y>=0.f)?vo.y:0.2f*vo.y;
            vo.z=(vo.z>=0.f)?vo.z:0.2f*vo.z; vo.w=(vo.w>=0.f)?vo.w:0.2f*vo.w;
        }
        *(float4*)(out + coe*HWSZ + o)     = ve;
        *(float4*)(out + (coe+1)*HWSZ + o) = vo;
    }
}

// ---------------- 5x5 conv, CIN->32, pad 2, lrelu, dual image ----------------
// tile 64x8; thread = 4 px x 16 co; ci chunked; row stride 68 (aligned)
template<int CIN, int CHUNK>
__global__ void __launch_bounds__(256, 2) conv5_k(
    const float* __restrict__ in0, const float* __restrict__ in1,
    const float* __restrict__ wt,  const float* __restrict__ bs,
    float* __restrict__ out0, float* __restrict__ out1)
{
    extern __shared__ float sm[];
    float* s_in = sm;                  // [CHUNK][12][68]
    float* s_w  = sm + CHUNK*816;      // [CHUNK][25][32co]
    const float* in = blockIdx.z ? in1 : in0;
    float* out      = blockIdx.z ? out1 : out0;
    const int tid = threadIdx.x;
    const int txg = tid & 15;
    const int ty  = (tid >> 4) & 7;
    const int cog = tid >> 7;
    const int ox0 = blockIdx.x*64, oy0 = blockIdx.y*8;

    u64 acc[4][8];
    #pragma unroll
    for (int cp = 0; cp < 8; cp++) {
        u64 b = pack2(__ldg(bs + cog*16 + 2*cp), __ldg(bs + cog*16 + 2*cp + 1));
        #pragma unroll
        for (int p = 0; p < 4; p++) acc[p][cp] = b;
    }

    for (int c0 = 0; c0 < CIN; c0 += CHUNK) {
        if (c0) __syncthreads();
        for (int i = tid; i < CHUNK*816; i += 256) {
            int ci = i / 816, rem = i % 816;
            int r = rem / 68, cc = rem % 68;
            int y = oy0 - 2 + r, x = ox0 - 2 + cc;
            s_in[i] = (y >= 0 && y < HH && x >= 0 && x < WW) ? in[(c0+ci)*HWSZ + y*WW + x] : 0.0f;
        }
        for (int i = tid; i < CHUNK*800; i += 256) {
            int ci = i / 800, rem = i % 800;
            int k = rem >> 5, co = rem & 31;
            s_w[i] = wt[(co*CIN + c0 + ci)*25 + k];
        }
        __syncthreads();

        for (int ci = 0; ci < CHUNK; ci++) {
            const float* base = s_in + ci*816 + ty*68 + txg*4;
            const float* wci  = s_w + ci*800 + cog*16;
            #pragma unroll
            for (int ky = 0; ky < 5; ky++) {
                const float* rp = base + ky*68;
                float4 a4 = *(const float4*)rp;
                float4 b4 = *(const float4*)(rp + 4);
                u64 vp[8];
                vp[0]=pack2(a4.x,a4.x); vp[1]=pack2(a4.y,a4.y); vp[2]=pack2(a4.z,a4.z);
                vp[3]=pack2(a4.w,a4.w); vp[4]=pack2(b4.x,b4.x); vp[5]=pack2(b4.y,b4.y);
                vp[6]=pack2(b4.z,b4.z); vp[7]=pack2(b4.w,b4.w);
                #pragma unroll
                for (int kx = 0; kx < 5; kx++) {
                    const float* wr = wci + (ky*5 + kx)*32;
                    u64 w[8];
                    #pragma unroll
                    for (int cp = 0; cp < 8; cp++) w[cp] = *(const u64*)(wr + 2*cp);
                    #pragma unroll
                    for (int p = 0; p < 4; p++)
                        #pragma unroll
                        for (int cp = 0; cp < 8; cp++)
                            acc[p][cp] = fma2(vp[p+kx], w[cp], acc[p][cp]);
                }
            }
        }
    }

    int o = (oy0 + ty)*WW + ox0 + txg*4;
    #pragma unroll
    for (int cp = 0; cp < 8; cp++) {
        int coe = cog*16 + 2*cp;
        float4 ve, vo;
        unpack2(acc[0][cp], ve.x, vo.x);
        unpack2(acc[1][cp], ve.y, vo.y);
        unpack2(acc[2][cp], ve.z, vo.z);
        unpack2(acc[3][cp], ve.w, vo.w);
        ve.x=(ve.x>=0.f)?ve.x:0.2f*ve.x; ve.y=(ve.y>=0.f)?ve.y:0.2f*ve.y;
        ve.z=(ve.z>=0.f)?ve.z:0.2f*ve.z; ve.w=(ve.w>=0.f)?ve.w:0.2f*ve.w;
        vo.x=(vo.x>=0.f)?vo.x:0.2f*vo.x; vo.y=(vo.y>=0.f)?vo.y:0.2f*vo.y;
        vo.z=(vo.z>=0.f)?vo.z:0.2f*vo.z; vo.w=(vo.w>=0.f)?vo.w:0.2f*vo.w;
        *(float4*)(out + coe*HWSZ + o)     = ve;
        *(float4*)(out + (coe+1)*HWSZ + o) = vo;
    }
}

// ---------------- fused 1x1 affine head + deformable 2x2 bilinear sampler ----
__device__ __forceinline__ int reflect_idx(int i) {  // xp coord -> x coord
    int r = i - 1;
    r = (r < 0) ? -r : r;
    r = (r > 319) ? (638 - r) : r;
    return r;
}

__global__ void sampler_k(const float* __restrict__ hid, const float* __restrict__ w2,
                          const float* __restrict__ b2, const float* __restrict__ x,
                          float* __restrict__ out) {
    __shared__ float s_w2[96];
    int tid = threadIdx.x;
    if (tid < 96) s_w2[tid] = w2[tid];
    __syncthreads();
    int p = blockIdx.x*256 + tid;                    // 102400 exact
    int h = p / WW, w = p % WW;

    float a0 = __ldg(b2 + 0), a1 = __ldg(b2 + 1), a2 = __ldg(b2 + 2);
    #pragma unroll 4
    for (int c = 0; c < 32; c++) {
        float hv = hid[c*HWSZ + p];
        a0 += hv*s_w2[c];
        a1 += hv*s_w2[32 + c];
        a2 += hv*s_w2[64 + c];
    }
    a0 = fminf(fmaxf(a0 + 1.0f, -3.0f), 3.0f);       // s_x
    a1 = fminf(fmaxf(a1 + 1.0f, -3.0f), 3.0f);       // s_y
    a2 = fminf(fmaxf(a2 + 1.0f, -3.0f), 3.0f);
    float th = (a2 - 1.0f)*1.0472f;
    float ct = cosf(th), st = sinf(th);

    int   idx[16];
    float wg[16];
    #pragma unroll
    for (int k = 0; k < 4; k++) {
        float pnx = (k & 2) ? 0.5f : -0.5f;
        float pny = (k & 1) ? 0.5f : -0.5f;
        float px = pnx*a0, py = pny*a1;
        float rx = px*ct - py*st;
        float ry = px*st + py*ct;
        float p_x = rx + 0.5f + (float)(h + 1);
        float p_y = ry + 0.5f + (float)(w + 1);
        float ltx = floorf(p_x), lty = floorf(p_y);
        float ltxc = fminf(fmaxf(ltx,        0.0f), 321.0f);
        float ltyc = fminf(fmaxf(lty,        0.0f), 321.0f);
        float rbxc = fminf(fmaxf(ltx + 1.0f, 0.0f), 321.0f);
        float rbyc = fminf(fmaxf(lty + 1.0f, 0.0f), 321.0f);
        float pxc  = fminf(fmaxf(p_x,        0.0f), 321.0f);
        float pyc  = fminf(fmaxf(p_y,        0.0f), 321.0f);
        float wlx = 1.0f + ltxc - pxc;
        float wrx = 1.0f - (rbxc - pxc);
        float wly = 1.0f + ltyc - pyc;
        float wry = 1.0f - (rbyc - pyc);
        int rl = reflect_idx((int)ltxc);
        int rr = reflect_idx((int)rbxc);
        int cl = reflect_idx((int)ltyc);
        int cr = reflect_idx((int)rbyc);
        idx[k*4+0] = rl*WW + cl;  wg[k*4+0] = wlx*wly;   // lt
        idx[k*4+1] = rr*WW + cr;  wg[k*4+1] = wrx*wry;   // rb
        idx[k*4+2] = rl*WW + cr;  wg[k*4+2] = wlx*wry;   // lb
        idx[k*4+3] = rr*WW + cl;  wg[k*4+3] = wrx*wly;   // rt
    }

    int ob = (2*h)*640 + 2*w;
    for (int c = 0; c < 64; c++) {
        const float* xc = x + c*HWSZ;
        float* oc = out + c*640*640;
        float v[4];
        #pragma unroll
        for (int k = 0; k < 4; k++) {
            v[k] = wg[k*4+0]*__ldg(xc + idx[k*4+0])
                 + wg[k*4+1]*__ldg(xc + idx[k*4+1])
                 + wg[k*4+2]*__ldg(xc + idx[k*4+2])
                 + wg[k*4+3]*__ldg(xc + idx[k*4+3]);
        }
        *(float2*)(oc + ob)       = make_float2(v[0], v[1]);
        *(float2*)(oc + ob + 640) = make_float2(v[2], v[3]);
    }
}

// ---------------- launch ------------------------------------------------------
extern "C" void kernel_launch(void* const* d_in, const int* in_sizes, int n_in,
                              void* d_out, int out_size) {
    const float* x    = (const float*)d_in[0];
    const float* qry  = (const float*)d_in[1];
    const float* ref  = (const float*)d_in[2];
    const float* c1w  = (const float*)d_in[3];
    const float* c1b  = (const float*)d_in[4];
    const float* r1w1 = (const float*)d_in[5];
    const float* r1b1 = (const float*)d_in[6];
    const float* r1w2 = (const float*)d_in[7];
    const float* r1b2 = (const float*)d_in[8];
    const float* p1w  = (const float*)d_in[9];
    const float* p1b  = (const float*)d_in[10];
    const float* prw1 = (const float*)d_in[11];
    const float* prb1 = (const float*)d_in[12];
    const float* prw2 = (const float*)d_in[13];
    const float* prb2 = (const float*)d_in[14];
    const float* p2w  = (const float*)d_in[15];
    const float* p2b  = (const float*)d_in[16];
    float* out = (float*)d_out;

    float *up, *feat, *buf1, *buf2, *hid;
    cudaGetSymbolAddress((void**)&up,   g_up);
    cudaGetSymbolAddress((void**)&feat, g_feat);
    cudaGetSymbolAddress((void**)&buf1, g_buf1);
    cudaGetSymbolAddress((void**)&buf2, g_buf2);
    cudaGetSymbolAddress((void**)&hid,  g_hid);

    const int SM3    = C3_SMEM;                 // 61952 B
    const int SM5_3  = (3*816 + 3*800)*4;       // 19392 B
    const int SM5_64 = (8*816 + 8*800)*4;       // 51712 B
    cudaFuncSetAttribute(conv3_k<0>, cudaFuncAttributeMaxDynamicSharedMemorySize, SM3);
    cudaFuncSetAttribute(conv3_k<1>, cudaFuncAttributeMaxDynamicSharedMemorySize, SM3);
    cudaFuncSetAttribute(conv5_k<3,3>,  cudaFuncAttributeMaxDynamicSharedMemorySize, SM5_3);
    cudaFuncSetAttribute(conv5_k<64,8>, cudaFuncAttributeMaxDynamicSharedMemorySize, SM5_64);

    dim3 cg2(5, 40, 2);   // 64x8 tiles, dual image
    dim3 cg1(5, 40, 1);

    // 1. bicubic upsample query 160->320
    bicubic_k<<<(3*HWSZ)/256, 256>>>(qry, up);

    // 2+3. both feature heads batched over gridDim.z
    conv5_k<3,3><<<cg2, 256, SM5_3>>>(ref, up, c1w, c1b, buf1, buf1 + 32*HWSZ);
    conv3_k<0><<<cg2, 256, SM3>>>(buf1, buf1 + 32*HWSZ, r1w1, r1b1,
                                  nullptr, nullptr, buf2, buf2 + 32*HWSZ);
    conv3_k<1><<<cg2, 256, SM3>>>(buf2, buf2 + 32*HWSZ, r1w2, r1b2,
                                  buf1, buf1 + 32*HWSZ, feat, feat + 32*HWSZ);

    // 4. fusion head
    conv5_k<64,8><<<cg1, 256, SM5_64>>>(feat, feat, p1w, p1b, buf1, buf1);
    conv3_k<0><<<cg1, 256, SM3>>>(buf1, buf1, prw1, prb1, nullptr, nullptr, buf2, buf2);
    conv3_k<1><<<cg1, 256, SM3>>>(buf2, buf2, prw2, prb2, buf1, buf1, hid, hid);

    // 5. fused 1x1 affine head + deformable sampler -> out (64,640,640)
    sampler_k<<<HWSZ/256, 256>>>(hid, p2w, p2b, x, out);
}